// round 11
// baseline (speedup 1.0000x reference)
#include <cuda_runtime.h>
#include <math.h>

// Greedy-collapsed beam search, persistent-grid decoder.
// Round-8 restructure: TPB=1024 (occ 50%), B1 = 4 rows/warp with packed
// fma.rn.f32x2 over batch pairs + fold-butterfly reduction, GRU reads
// weights exactly once per step (j-per-warp-half), max-free softmax.

#define NCTA  148
#define TPB   1024
#define VOCAB 16000
#define EDIM  256
#define HDIM  512
#define BATCH 8
#define PAD_ID 0
#define SOS_ID 1
#define EOS_ID 2

typedef unsigned long long ull;

__device__ float    g_h[2][BATCH * HDIM];
__device__ float4   g_part[NCTA][BATCH];   // x=max, y=sumexp(abs), z=argmax idx bits
__device__ unsigned g_bar;

__global__ void decoder_init(const float* __restrict__ hidden) {
    int t = blockIdx.x * blockDim.x + threadIdx.x;
    if (t < BATCH * HDIM) g_h[0][t] = hidden[t];
    if (t == 0) g_bar = 0u;
}

__device__ __forceinline__ ull fma2(ull a, ull b, ull c) {
    ull d; asm("fma.rn.f32x2 %0, %1, %2, %3;" : "=l"(d) : "l"(a), "l"(b), "l"(c)); return d;
}
__device__ __forceinline__ ull add2(ull a, ull b) {
    ull d; asm("add.rn.f32x2 %0, %1, %2;" : "=l"(d) : "l"(a), "l"(b)); return d;
}
__device__ __forceinline__ ull bcast2(float x) {
    ull d; asm("mov.b64 %0, {%1, %1};" : "=l"(d) : "r"(__float_as_uint(x))); return d;
}

__device__ __forceinline__ void grid_sync(unsigned target) {
    __syncthreads();
    if (threadIdx.x == 0) {
        __threadfence();
        atomicAdd(&g_bar, 1u);
        while (*(volatile unsigned*)&g_bar < target) {}
        __threadfence();
    }
    __syncthreads();
}

// Stage h (4096 floats) into two smem layouts:
//   s_h03[d] = {h0[d],h1[d],h2[d],h3[d]}, s_h47 likewise  (for B1 packed loads)
//   s_hn[b*516 + d] = h[b][d]                              (for GRU float4 loads)
__device__ __forceinline__ void stage_h(const float* src, float4* s_h03, float4* s_h47,
                                        float* s_hn, int tid) {
    float4 v = __ldcg((const float4*)src + tid);   // tid in [0,1024): one float4 each
    const int b = tid >> 7;
    const int d = (tid & 127) * 4;
    *(float4*)&s_hn[b * 516 + d] = v;
    float* t03 = (b < 4) ? (float*)s_h03 : (float*)s_h47;
    const int bb = b & 3;
    t03[(d + 0) * 4 + bb] = v.x;
    t03[(d + 1) * 4 + bb] = v.y;
    t03[(d + 2) * 4 + bb] = v.z;
    t03[(d + 3) * 4 + bb] = v.w;
}

__global__ void __launch_bounds__(TPB, 1) decoder_main(
    const float* __restrict__ embedding,
    const float* __restrict__ w_ih,
    const float* __restrict__ w_hh,
    const float* __restrict__ b_ih,
    const float* __restrict__ b_hh,
    const float* __restrict__ w_out,
    const float* __restrict__ b_out,
    float* __restrict__ out,
    int lenseq)
{
    __shared__ float4 s_h03[HDIM];            // 8 KB
    __shared__ float4 s_h47[HDIM];            // 8 KB
    __shared__ float  s_hn[BATCH * 516];      // 16.1 KB (516 = pad for bank spread)
    __shared__ float  s_log[112][9];          // 4 KB, stride-9 = conflict-free
    __shared__ float  s_S[BATCH];
    __shared__ int    s_tok[BATCH], s_done[BATCH];

    const int tid  = threadIdx.x;
    const int wp   = tid >> 5;
    const int lane = tid & 31;
    const int cta  = blockIdx.x;
    const int base  = cta * 108 + (cta < 16 ? cta : 16);
    const int nrows = 108 + (cta < 16 ? 1 : 0);

    // GRU task: 1024 tasks = 512 j's x 2 batch-halves, spread across CTAs
    const int  task   = wp * NCTA + cta;
    const bool gru_on = task < 2 * HDIM;
    const int  gj     = task >> 1;
    const int  gb     = (task & 1) * 4 + (lane >> 3);  // batch
    const int  gg     = lane & 7;                       // dim group

    if (tid < BATCH) s_tok[tid] = SOS_ID;
    stage_h(g_h[0], s_h03, s_h47, s_hn, tid);
    __syncthreads();

    unsigned bt = 0;
    int cur = 0;

    for (int step = 0; step < lenseq; ++step) {
        const int nxt = cur ^ 1;

        // ================= Phase A: GRU (weights read once chip-wide) ========
        if (gru_on) {
            const int tok = s_tok[gb];
            float ir = 0.f, iz = 0.f, in_ = 0.f;
            const float4* e4  = (const float4*)(embedding + (size_t)tok * EDIM);
            const float4* air = (const float4*)(w_ih + (size_t)gj * EDIM);
            const float4* aiz = (const float4*)(w_ih + (size_t)(gj + HDIM) * EDIM);
            const float4* ain = (const float4*)(w_ih + (size_t)(gj + 2 * HDIM) * EDIM);
            #pragma unroll
            for (int it = 0; it < 8; ++it) {
                const int c = gg * 8 + it;
                float4 e = e4[c];
                float4 a = air[c]; ir  += e.x*a.x + e.y*a.y + e.z*a.z + e.w*a.w;
                float4 z = aiz[c]; iz  += e.x*z.x + e.y*z.y + e.z*z.z + e.w*z.w;
                float4 n = ain[c]; in_ += e.x*n.x + e.y*n.y + e.z*n.z + e.w*n.w;
            }
            float hr = 0.f, hz = 0.f, hn = 0.f;
            const float4* uhr = (const float4*)(w_hh + (size_t)gj * HDIM);
            const float4* uhz = (const float4*)(w_hh + (size_t)(gj + HDIM) * HDIM);
            const float4* uhn = (const float4*)(w_hh + (size_t)(gj + 2 * HDIM) * HDIM);
            const float*  hb  = s_hn + gb * 516;
            #pragma unroll 4
            for (int it = 0; it < 16; ++it) {
                const int c = gg * 16 + it;
                float4 h = *(const float4*)&hb[c * 4];
                float4 a = uhr[c]; hr += h.x*a.x + h.y*a.y + h.z*a.z + h.w*a.w;
                float4 z = uhz[c]; hz += h.x*z.x + h.y*z.y + h.z*z.z + h.w*z.w;
                float4 n = uhn[c]; hn += h.x*n.x + h.y*n.y + h.z*n.z + h.w*n.w;
            }
            #pragma unroll
            for (int off = 1; off < 8; off <<= 1) {
                ir  += __shfl_xor_sync(~0u, ir,  off);
                iz  += __shfl_xor_sync(~0u, iz,  off);
                in_ += __shfl_xor_sync(~0u, in_, off);
                hr  += __shfl_xor_sync(~0u, hr,  off);
                hz  += __shfl_xor_sync(~0u, hz,  off);
                hn  += __shfl_xor_sync(~0u, hn,  off);
            }
            if (gg == 0) {
                const float hold = hb[gj];
                float hv;
                if (tok == PAD_ID || tok == EOS_ID) {
                    hv = hold;
                } else {
                    const float rg = 1.f / (1.f + expf(-(ir + b_ih[gj]            + hr + b_hh[gj])));
                    const float zg = 1.f / (1.f + expf(-(iz + b_ih[gj + HDIM]     + hz + b_hh[gj + HDIM])));
                    const float ng = tanhf(in_ + b_ih[gj + 2 * HDIM] + rg * (hn + b_hh[gj + 2 * HDIM]));
                    hv = (1.f - zg) * ng + zg * hold;
                }
                g_h[nxt][gb * HDIM + gj] = hv;
            }
        }
        bt += NCTA; grid_sync(bt);

        // ================= Stage h(nxt) into smem ============================
        stage_h(g_h[nxt], s_h03, s_h47, s_hn, tid);
        __syncthreads();

        // ================= Phase B1: logits, 4 rows/warp, packed f32x2 =======
        {
            const int r0c = min(wp,      nrows - 1);
            const int r1c = min(wp + 32, nrows - 1);
            const int r2c = min(wp + 64, nrows - 1);
            const int r3c = min(wp + 96, nrows - 1);
            const float* w0 = w_out + (size_t)(base + r0c) * HDIM;
            const float* w1 = w_out + (size_t)(base + r1c) * HDIM;
            const float* w2 = w_out + (size_t)(base + r2c) * HDIM;
            const float* w3 = w_out + (size_t)(base + r3c) * HDIM;
            ull v[16];
            #pragma unroll
            for (int i = 0; i < 16; i++) v[i] = 0ull;
            #pragma unroll 4
            for (int k = 0; k < 16; k++) {
                const int d = k * 32 + lane;                       // coalesced dims
                const ulonglong2 hA = *(const ulonglong2*)&s_h03[d];  // {h01,h23}
                const ulonglong2 hB = *(const ulonglong2*)&s_h47[d];  // {h45,h67}
                ull wb;
                wb = bcast2(w0[d]);
                v[0]=fma2(wb,hA.x,v[0]);  v[1]=fma2(wb,hA.y,v[1]);
                v[2]=fma2(wb,hB.x,v[2]);  v[3]=fma2(wb,hB.y,v[3]);
                wb = bcast2(w1[d]);
                v[4]=fma2(wb,hA.x,v[4]);  v[5]=fma2(wb,hA.y,v[5]);
                v[6]=fma2(wb,hB.x,v[6]);  v[7]=fma2(wb,hB.y,v[7]);
                wb = bcast2(w2[d]);
                v[8]=fma2(wb,hA.x,v[8]);  v[9]=fma2(wb,hA.y,v[9]);
                v[10]=fma2(wb,hB.x,v[10]); v[11]=fma2(wb,hB.y,v[11]);
                wb = bcast2(w3[d]);
                v[12]=fma2(wb,hA.x,v[12]); v[13]=fma2(wb,hA.y,v[13]);
                v[14]=fma2(wb,hB.x,v[14]); v[15]=fma2(wb,hB.y,v[15]);
            }
            // fold-butterfly: 16 accs x 32 lanes -> each lane-pair one total
            #pragma unroll
            for (int i = 0; i < 8; i++) {
                ull give = (lane & 16) ? v[i] : v[i + 8];
                ull keep = (lane & 16) ? v[i + 8] : v[i];
                v[i] = add2(keep, __shfl_xor_sync(~0u, give, 16));
            }
            #pragma unroll
            for (int i = 0; i < 4; i++) {
                ull give = (lane & 8) ? v[i] : v[i + 4];
                ull keep = (lane & 8) ? v[i + 4] : v[i];
                v[i] = add2(keep, __shfl_xor_sync(~0u, give, 8));
            }
            #pragma unroll
            for (int i = 0; i < 2; i++) {
                ull give = (lane & 4) ? v[i] : v[i + 2];
                ull keep = (lane & 4) ? v[i + 2] : v[i];
                v[i] = add2(keep, __shfl_xor_sync(~0u, give, 4));
            }
            {
                ull give = (lane & 2) ? v[0] : v[1];
                ull keep = (lane & 2) ? v[1] : v[0];
                v[0] = add2(keep, __shfl_xor_sync(~0u, give, 2));
            }
            v[0] = add2(v[0], __shfl_xor_sync(~0u, v[0], 1));
            // lane l holds total for row index (l>>3)&3, batch-pair (l>>1)&3
            if (!(lane & 1)) {
                const int i = (lane >> 3) & 3;
                const int p = (lane >> 1) & 3;
                const int r = wp + 32 * i;
                if (r < nrows) {
                    const float bo = b_out[base + r];
                    const float2 lv = *(float2*)&v[0];
                    s_log[r][2 * p]     = lv.x + bo;
                    s_log[r][2 * p + 1] = lv.y + bo;
                }
            }
        }
        __syncthreads();

        // ============ per-CTA partial: abs-sumexp + argmax (warps 0-7) =======
        if (wp < BATCH) {
            const int b = wp;
            float m = -INFINITY, s = 0.f; int mi = 0x7fffffff;
            for (int r = lane; r < nrows; r += 32) {
                const float vv = s_log[r][b];
                s += __expf(vv);
                if (vv > m) { m = vv; mi = base + r; }
            }
            #pragma unroll
            for (int off = 16; off; off >>= 1) {
                const float om = __shfl_xor_sync(~0u, m, off);
                const int   oi = __shfl_xor_sync(~0u, mi, off);
                s += __shfl_xor_sync(~0u, s, off);
                if (om > m || (om == m && oi < mi)) { m = om; mi = oi; }
            }
            if (lane == 0) g_part[cta][b] = make_float4(m, s, __int_as_float(mi), 0.f);
        }
        bt += NCTA; grid_sync(bt);

        // ============ Phase B2: global reduce (redundant per CTA) ============
        if (wp < BATCH) {
            const int b = wp;
            float m = -INFINITY, S = 0.f; int mi = 0x7fffffff;
            for (int c = lane; c < NCTA; c += 32) {
                const float4 pr = __ldcg(&g_part[c][b]);
                S += pr.y;
                const int oi = __float_as_int(pr.z);
                if (pr.x > m || (pr.x == m && oi < mi)) { m = pr.x; mi = oi; }
            }
            #pragma unroll
            for (int off = 16; off; off >>= 1) {
                const float om = __shfl_xor_sync(~0u, m, off);
                const int   oi = __shfl_xor_sync(~0u, mi, off);
                S += __shfl_xor_sync(~0u, S, off);
                if (om > m || (om == m && oi < mi)) { m = om; mi = oi; }
            }
            if (lane == 0) {
                const int old = s_tok[b];
                const int d = (old == PAD_ID) | (old == EOS_ID);
                s_done[b] = d;
                s_S[b]    = S;
                s_tok[b]  = d ? PAD_ID : mi;    // done -> PAD forever
            }
        }
        __syncthreads();

        // ============ Phase C: coalesced probability write ===================
        {
            const int b  = tid >> 7;        // 8 groups of 128 threads
            const int rr = tid & 127;
            if (rr < nrows) {
                float* o = out + ((size_t)step * BATCH + b) * VOCAB + base;
                if (s_done[b]) o[rr] = (base + rr == PAD_ID) ? 1.f : 0.f;
                else           o[rr] = __fdividef(__expf(s_log[rr][b]), s_S[b]);
            }
        }
        cur = nxt;
    }
}

extern "C" void kernel_launch(void* const* d_in, const int* in_sizes, int n_in,
                              void* d_out, int out_size) {
    const float* hidden    = (const float*)d_in[0];
    const float* embedding = (const float*)d_in[1];
    const float* w_ih      = (const float*)d_in[2];
    const float* w_hh      = (const float*)d_in[3];
    const float* b_ih      = (const float*)d_in[4];
    const float* b_hh      = (const float*)d_in[5];
    const float* w_out     = (const float*)d_in[6];
    const float* b_out     = (const float*)d_in[7];
    float* out = (float*)d_out;
    (void)in_sizes; (void)n_in;

    const int lenseq = out_size / (BATCH * VOCAB);
    if (lenseq <= 0) return;

    decoder_init<<<16, 256>>>(hidden);
    decoder_main<<<NCTA, TPB>>>(embedding, w_ih, w_hh, b_ih, b_hh,
                                w_out, b_out, out, lenseq);
}

// round 12
// speedup vs baseline: 1.0112x; 1.0112x over previous
#include <cuda_runtime.h>
#include <math.h>

// Greedy-collapsed beam search, persistent-grid decoder.
// Round-12: TPB=512 / 128 regs (kill spills), B1 = 8 rows x 8 batches per warp
// (32 ull f32x2 accumulators, 5-fold butterfly -> 1 value per lane), Phase C
// (prev-step writes) overlapped with GRU of the current step.

#define NCTA  148
#define TPB   512
#define VOCAB 16000
#define EDIM  256
#define HDIM  512
#define BATCH 8
#define PAD_ID 0
#define SOS_ID 1
#define EOS_ID 2

typedef unsigned long long ull;

__device__ float    g_h[2][BATCH * HDIM];
__device__ float4   g_part[NCTA][BATCH];   // x=max, y=sumexp(abs), z=argmax idx bits
__device__ unsigned g_bar;

__global__ void decoder_init(const float* __restrict__ hidden) {
    int t = blockIdx.x * blockDim.x + threadIdx.x;
    if (t < BATCH * HDIM) g_h[0][t] = hidden[t];
    if (t == 0) g_bar = 0u;
}

__device__ __forceinline__ ull fma2(ull a, ull b, ull c) {
    ull d; asm("fma.rn.f32x2 %0, %1, %2, %3;" : "=l"(d) : "l"(a), "l"(b), "l"(c)); return d;
}
__device__ __forceinline__ ull add2(ull a, ull b) {
    ull d; asm("add.rn.f32x2 %0, %1, %2;" : "=l"(d) : "l"(a), "l"(b)); return d;
}
__device__ __forceinline__ ull bcast2(float x) {
    ull d; asm("mov.b64 %0, {%1, %1};" : "=l"(d) : "r"(__float_as_uint(x))); return d;
}

__device__ __forceinline__ void grid_sync(unsigned target) {
    __syncthreads();
    if (threadIdx.x == 0) {
        __threadfence();
        atomicAdd(&g_bar, 1u);
        while (*(volatile unsigned*)&g_bar < target) {}
        __threadfence();
    }
    __syncthreads();
}

// Stage h (4096 floats): batch-packed layout for B1 + linear layout for GRU.
__device__ __forceinline__ void stage_h(const float* src, float4* s_h03, float4* s_h47,
                                        float* s_hn, int tid) {
    #pragma unroll
    for (int t = tid; t < BATCH * HDIM / 4; t += TPB) {
        float4 v = __ldcg((const float4*)src + t);
        const int b = t >> 7;
        const int d = (t & 127) * 4;
        *(float4*)&s_hn[b * 516 + d] = v;
        float* t03 = (b < 4) ? (float*)s_h03 : (float*)s_h47;
        const int bb = b & 3;
        t03[(d + 0) * 4 + bb] = v.x;
        t03[(d + 1) * 4 + bb] = v.y;
        t03[(d + 2) * 4 + bb] = v.z;
        t03[(d + 3) * 4 + bb] = v.w;
    }
}

__global__ void __launch_bounds__(TPB, 1) decoder_main(
    const float* __restrict__ embedding,
    const float* __restrict__ w_ih,
    const float* __restrict__ w_hh,
    const float* __restrict__ b_ih,
    const float* __restrict__ b_hh,
    const float* __restrict__ w_out,
    const float* __restrict__ b_out,
    float* __restrict__ out,
    int lenseq)
{
    __shared__ float4 s_h03[HDIM];            // 8 KB  {h0..h3}[d]
    __shared__ float4 s_h47[HDIM];            // 8 KB  {h4..h7}[d]
    __shared__ float  s_hn[BATCH * 516];      // 16.1 KB linear (GRU)
    __shared__ float  s_log[112][9];          // 3.9 KB stride-9
    __shared__ float  s_S[BATCH];
    __shared__ int    s_tok[BATCH], s_done[BATCH];

    const int tid  = threadIdx.x;
    const int wp   = tid >> 5;
    const int lane = tid & 31;
    const int cta  = blockIdx.x;
    const int base  = cta * 108 + (cta < 16 ? cta : 16);
    const int nrows = 108 + (cta < 16 ? 1 : 0);

    // GRU tasks: 1024 = 512 j x 2 batch-halves; warps 0-6 of each CTA
    const int  task   = wp * NCTA + cta;
    const bool gru_on = task < 2 * HDIM;
    const int  gj     = task >> 1;
    const int  gb     = (task & 1) * 4 + (lane >> 3);
    const int  gg     = lane & 7;

    if (tid < BATCH) s_tok[tid] = SOS_ID;
    stage_h(g_h[0], s_h03, s_h47, s_hn, tid);
    __syncthreads();

    unsigned bt = 0;
    int cur = 0;

    for (int step = 0; step < lenseq; ++step) {
        const int nxt = cur ^ 1;

        // ===== Phase A: GRU (warps 0-6)  ||  Phase C of step-1 (warps 8-15) ==
        if (gru_on) {
            const int tok = s_tok[gb];
            float ir = 0.f, iz = 0.f, in_ = 0.f;
            const float4* e4  = (const float4*)(embedding + (size_t)tok * EDIM);
            const float4* air = (const float4*)(w_ih + (size_t)gj * EDIM);
            const float4* aiz = (const float4*)(w_ih + (size_t)(gj + HDIM) * EDIM);
            const float4* ain = (const float4*)(w_ih + (size_t)(gj + 2 * HDIM) * EDIM);
            #pragma unroll
            for (int it = 0; it < 8; ++it) {
                const int c = gg * 8 + it;
                float4 e = e4[c];
                float4 a = air[c]; ir  += e.x*a.x + e.y*a.y + e.z*a.z + e.w*a.w;
                float4 z = aiz[c]; iz  += e.x*z.x + e.y*z.y + e.z*z.z + e.w*z.w;
                float4 n = ain[c]; in_ += e.x*n.x + e.y*n.y + e.z*n.z + e.w*n.w;
            }
            float hr = 0.f, hz = 0.f, hn = 0.f;
            const float4* uhr = (const float4*)(w_hh + (size_t)gj * HDIM);
            const float4* uhz = (const float4*)(w_hh + (size_t)(gj + HDIM) * HDIM);
            const float4* uhn = (const float4*)(w_hh + (size_t)(gj + 2 * HDIM) * HDIM);
            const float*  hb  = s_hn + gb * 516;
            #pragma unroll 4
            for (int it = 0; it < 16; ++it) {
                const int c = gg * 16 + it;
                float4 h = *(const float4*)&hb[c * 4];
                float4 a = uhr[c]; hr += h.x*a.x + h.y*a.y + h.z*a.z + h.w*a.w;
                float4 z = uhz[c]; hz += h.x*z.x + h.y*z.y + h.z*z.z + h.w*z.w;
                float4 n = uhn[c]; hn += h.x*n.x + h.y*n.y + h.z*n.z + h.w*n.w;
            }
            #pragma unroll
            for (int off = 1; off < 8; off <<= 1) {
                ir  += __shfl_xor_sync(~0u, ir,  off);
                iz  += __shfl_xor_sync(~0u, iz,  off);
                in_ += __shfl_xor_sync(~0u, in_, off);
                hr  += __shfl_xor_sync(~0u, hr,  off);
                hz  += __shfl_xor_sync(~0u, hz,  off);
                hn  += __shfl_xor_sync(~0u, hn,  off);
            }
            if (gg == 0) {
                const float hold = hb[gj];
                float hv;
                if (tok == PAD_ID || tok == EOS_ID) {
                    hv = hold;
                } else {
                    const float rg = 1.f / (1.f + expf(-(ir + b_ih[gj]            + hr + b_hh[gj])));
                    const float zg = 1.f / (1.f + expf(-(iz + b_ih[gj + HDIM]     + hz + b_hh[gj + HDIM])));
                    const float ng = tanhf(in_ + b_ih[gj + 2 * HDIM] + rg * (hn + b_hh[gj + 2 * HDIM]));
                    hv = (1.f - zg) * ng + zg * hold;
                }
                g_h[nxt][gb * HDIM + gj] = hv;
            }
        } else if (wp >= 8 && step > 0) {
            // Phase C for step-1 (off the critical path)
            const int b = wp - 8;
            float* o = out + ((size_t)(step - 1) * BATCH + b) * VOCAB + base;
            if (s_done[b]) {
                for (int r = lane; r < nrows; r += 32)
                    o[r] = (base + r == PAD_ID) ? 1.f : 0.f;
            } else {
                const float S = s_S[b];
                for (int r = lane; r < nrows; r += 32)
                    o[r] = __fdividef(__expf(s_log[r][b]), S);
            }
        }
        bt += NCTA; grid_sync(bt);

        // ===== Stage h(nxt) into smem ========================================
        stage_h(g_h[nxt], s_h03, s_h47, s_hn, tid);
        __syncthreads();

        // ===== Phase B1: logits, 8 rows x 8 batches per warp (warps 0-13) ===
        if (wp < 14) {
            const int rb = min(wp * 8, nrows - 8);          // clamped window
            const float* wr = w_out + (size_t)(base + rb) * HDIM;
            ull v[32];
            #pragma unroll
            for (int i = 0; i < 32; i++) v[i] = 0ull;
            #pragma unroll 2
            for (int k = 0; k < 16; k++) {
                const int d = k * 32 + lane;
                const ulonglong2 hA = *(const ulonglong2*)&s_h03[d]; // {b01,b23}
                const ulonglong2 hB = *(const ulonglong2*)&s_h47[d]; // {b45,b67}
                #pragma unroll
                for (int r = 0; r < 8; r++) {
                    const ull wb = bcast2(wr[(size_t)r * HDIM + d]);
                    v[r*4+0] = fma2(wb, hA.x, v[r*4+0]);
                    v[r*4+1] = fma2(wb, hA.y, v[r*4+1]);
                    v[r*4+2] = fma2(wb, hB.x, v[r*4+2]);
                    v[r*4+3] = fma2(wb, hB.y, v[r*4+3]);
                }
            }
            // 5-fold butterfly: 32 accs x 32 lanes -> lane L owns slot
            // r=(L>>2)&7, p=L&3  (slot i = r*4+p)
            #pragma unroll
            for (int i = 0; i < 16; i++) {
                ull g = (lane & 16) ? v[i] : v[i + 16];
                ull kp = (lane & 16) ? v[i + 16] : v[i];
                v[i] = add2(kp, __shfl_xor_sync(~0u, g, 16));
            }
            #pragma unroll
            for (int i = 0; i < 8; i++) {
                ull g = (lane & 8) ? v[i] : v[i + 8];
                ull kp = (lane & 8) ? v[i + 8] : v[i];
                v[i] = add2(kp, __shfl_xor_sync(~0u, g, 8));
            }
            #pragma unroll
            for (int i = 0; i < 4; i++) {
                ull g = (lane & 4) ? v[i] : v[i + 4];
                ull kp = (lane & 4) ? v[i + 4] : v[i];
                v[i] = add2(kp, __shfl_xor_sync(~0u, g, 4));
            }
            #pragma unroll
            for (int i = 0; i < 2; i++) {
                ull g = (lane & 2) ? v[i] : v[i + 2];
                ull kp = (lane & 2) ? v[i + 2] : v[i];
                v[i] = add2(kp, __shfl_xor_sync(~0u, g, 2));
            }
            {
                ull g = (lane & 1) ? v[0] : v[1];
                ull kp = (lane & 1) ? v[1] : v[0];
                v[0] = add2(kp, __shfl_xor_sync(~0u, g, 1));
            }
            const int r   = (lane >> 2) & 7;
            const int p   = lane & 3;
            const int row = rb + r;                          // always < nrows
            const float bo = b_out[base + row];
            const float2 lv = *(float2*)&v[0];
            s_log[row][2 * p]     = lv.x + bo;
            s_log[row][2 * p + 1] = lv.y + bo;
        }
        __syncthreads();

        // ===== per-CTA partial: abs-sumexp + argmax (warps 0-7) ==============
        if (wp < BATCH) {
            const int b = wp;
            float m = -INFINITY, s = 0.f; int mi = 0x7fffffff;
            for (int r = lane; r < nrows; r += 32) {
                const float vv = s_log[r][b];
                s += __expf(vv);
                if (vv > m) { m = vv; mi = base + r; }
            }
            #pragma unroll
            for (int off = 16; off; off >>= 1) {
                const float om = __shfl_xor_sync(~0u, m, off);
                const int   oi = __shfl_xor_sync(~0u, mi, off);
                s += __shfl_xor_sync(~0u, s, off);
                if (om > m || (om == m && oi < mi)) { m = om; mi = oi; }
            }
            if (lane == 0) g_part[cta][b] = make_float4(m, s, __int_as_float(mi), 0.f);
        }
        bt += NCTA; grid_sync(bt);

        // ===== Phase B2: global reduce (redundant per CTA) ===================
        if (wp < BATCH) {
            const int b = wp;
            float m = -INFINITY, S = 0.f; int mi = 0x7fffffff;
            for (int c = lane; c < NCTA; c += 32) {
                const float4 pr = __ldcg(&g_part[c][b]);
                S += pr.y;
                const int oi = __float_as_int(pr.z);
                if (pr.x > m || (pr.x == m && oi < mi)) { m = pr.x; mi = oi; }
            }
            #pragma unroll
            for (int off = 16; off; off >>= 1) {
                const float om = __shfl_xor_sync(~0u, m, off);
                const int   oi = __shfl_xor_sync(~0u, mi, off);
                S += __shfl_xor_sync(~0u, S, off);
                if (om > m || (om == m && oi < mi)) { m = om; mi = oi; }
            }
            if (lane == 0) {
                const int old = s_tok[b];
                const int d = (old == PAD_ID) | (old == EOS_ID);
                s_done[b] = d;
                s_S[b]    = S;
                s_tok[b]  = d ? PAD_ID : mi;
            }
        }
        __syncthreads();
        cur = nxt;
    }

    // ===== Final Phase C: write last step's probabilities (all warps) ========
    {
        const int b  = tid >> 6;            // 8 groups of 64 threads
        const int r0 = tid & 63;
        float* o = out + ((size_t)(lenseq - 1) * BATCH + b) * VOCAB + base;
        if (s_done[b]) {
            for (int r = r0; r < nrows; r += 64)
                o[r] = (base + r == PAD_ID) ? 1.f : 0.f;
        } else {
            const float S = s_S[b];
            for (int r = r0; r < nrows; r += 64)
                o[r] = __fdividef(__expf(s_log[r][b]), S);
        }
    }
}

extern "C" void kernel_launch(void* const* d_in, const int* in_sizes, int n_in,
                              void* d_out, int out_size) {
    const float* hidden    = (const float*)d_in[0];
    const float* embedding = (const float*)d_in[1];
    const float* w_ih      = (const float*)d_in[2];
    const float* w_hh      = (const float*)d_in[3];
    const float* b_ih      = (const float*)d_in[4];
    const float* b_hh      = (const float*)d_in[5];
    const float* w_out     = (const float*)d_in[6];
    const float* b_out     = (const float*)d_in[7];
    float* out = (float*)d_out;
    (void)in_sizes; (void)n_in;

    const int lenseq = out_size / (BATCH * VOCAB);
    if (lenseq <= 0) return;

    decoder_init<<<16, 256>>>(hidden);
    decoder_main<<<NCTA, TPB>>>(embedding, w_ih, w_hh, b_ih, b_hh,
                                w_out, b_out, out, lenseq);
}

// round 13
// speedup vs baseline: 1.6262x; 1.6082x over previous
#include <cuda_runtime.h>
#include <math.h>

// Greedy-collapsed beam search, persistent-grid decoder.
// Round-13: acquire/release barriers (no MEMBAR.GL), split counter/flag cache
// lines, CTA0-centralized softmax reduce (no 148x redundant L2 storm),
// conflict-free h staging (thread-per-dim transpose), coalesced GRU loads.

#define NCTA  148
#define TPB   512
#define VOCAB 16000
#define EDIM  256
#define HDIM  512
#define BATCH 8
#define PAD_ID 0
#define SOS_ID 1
#define EOS_ID 2

typedef unsigned long long ull;

__device__ float    g_h[2][BATCH * HDIM];
__device__ float4   g_part[NCTA][BATCH];          // x=max, y=sumexp, z=argmax bits
__device__ __align__(128) unsigned g_c1[32];      // bar1 arrival counter (own line)
__device__ __align__(128) unsigned g_f1[32];      // bar1 release flag    (own line)
__device__ __align__(128) unsigned g_c2[32];      // bar2 arrival counter
__device__ __align__(128) unsigned g_f2[32];      // bar2 release flag
__device__ __align__(128) uint2    g_res[BATCH];  // x=argmax token, y=S bits

__global__ void decoder_init(const float* __restrict__ hidden) {
    int t = blockIdx.x * blockDim.x + threadIdx.x;
    if (t < BATCH * HDIM) g_h[0][t] = hidden[t];
    if (t == 0) { g_c1[0] = 0; g_f1[0] = 0; g_c2[0] = 0; g_f2[0] = 0; }
}

__device__ __forceinline__ ull fma2(ull a, ull b, ull c) {
    ull d; asm("fma.rn.f32x2 %0, %1, %2, %3;" : "=l"(d) : "l"(a), "l"(b), "l"(c)); return d;
}
__device__ __forceinline__ ull add2(ull a, ull b) {
    ull d; asm("add.rn.f32x2 %0, %1, %2;" : "=l"(d) : "l"(a), "l"(b)); return d;
}
__device__ __forceinline__ ull bcast2(float x) {
    ull d; asm("mov.b64 %0, {%1, %1};" : "=l"(d) : "r"(__float_as_uint(x))); return d;
}

__device__ __forceinline__ void red_release(unsigned* p) {
    asm volatile("red.release.gpu.global.add.u32 [%0], %1;" :: "l"(p), "r"(1u) : "memory");
}
__device__ __forceinline__ unsigned ld_acquire(unsigned* p) {
    unsigned v; asm volatile("ld.global.acquire.gpu.b32 %0, [%1];" : "=r"(v) : "l"(p) : "memory"); return v;
}
__device__ __forceinline__ void st_release(unsigned* p, unsigned v) {
    asm volatile("st.global.release.gpu.b32 [%0], %1;" :: "l"(p), "r"(v) : "memory");
}

// Thread-per-dim transpose staging: tid d owns dim d (TPB==HDIM).
// 8 coalesced LDG (2KB apart), conflict-free STS.
__device__ __forceinline__ void stage_h(const float* src, float4* s_h03, float4* s_h47,
                                        float* s_hn, int tid) {
    float v[BATCH];
    #pragma unroll
    for (int b = 0; b < BATCH; b++) v[b] = __ldcg(src + b * HDIM + tid);
    s_h03[tid] = make_float4(v[0], v[1], v[2], v[3]);
    s_h47[tid] = make_float4(v[4], v[5], v[6], v[7]);
    #pragma unroll
    for (int b = 0; b < BATCH; b++) s_hn[b * 516 + tid] = v[b];
}

__global__ void __launch_bounds__(TPB, 1) decoder_main(
    const float* __restrict__ embedding,
    const float* __restrict__ w_ih,
    const float* __restrict__ w_hh,
    const float* __restrict__ b_ih,
    const float* __restrict__ b_hh,
    const float* __restrict__ w_out,
    const float* __restrict__ b_out,
    float* __restrict__ out,
    int lenseq)
{
    __shared__ float4 s_h03[HDIM];            // {h0..h3}[d]
    __shared__ float4 s_h47[HDIM];            // {h4..h7}[d]
    __shared__ float  s_hn[BATCH * 516];      // linear h for GRU
    __shared__ float  s_log[112][9];          // stride-9 conflict-free
    __shared__ float  s_S[BATCH];
    __shared__ int    s_tok[BATCH], s_done[BATCH];

    const int tid  = threadIdx.x;
    const int wp   = tid >> 5;
    const int lane = tid & 31;
    const int cta  = blockIdx.x;
    const int base  = cta * 108 + (cta < 16 ? cta : 16);
    const int nrows = 108 + (cta < 16 ? 1 : 0);

    // GRU tasks: 1024 = 512 j x 2 batch-halves; warps 0-6 of each CTA
    const int  task   = wp * NCTA + cta;
    const bool gru_on = task < 2 * HDIM;
    const int  gj     = task >> 1;
    const int  gb     = (task & 1) * 4 + (lane >> 3);
    const int  gg     = lane & 7;

    if (tid < BATCH) s_tok[tid] = SOS_ID;
    stage_h(g_h[0], s_h03, s_h47, s_hn, tid);
    __syncthreads();

    unsigned bt = 0;

    for (int step = 0; step < lenseq; ++step) {
        const int nxt = (step & 1) ^ 1;
        bt += NCTA;

        // ===== Phase A: GRU (warps 0-6)  ||  Phase C of step-1 (warps 8-15) ==
        if (gru_on) {
            const int tok = s_tok[gb];
            float ir = 0.f, iz = 0.f, in_ = 0.f;
            const float4* e4  = (const float4*)(embedding + (size_t)tok * EDIM);
            const float4* air = (const float4*)(w_ih + (size_t)gj * EDIM);
            const float4* aiz = (const float4*)(w_ih + (size_t)(gj + HDIM) * EDIM);
            const float4* ain = (const float4*)(w_ih + (size_t)(gj + 2 * HDIM) * EDIM);
            #pragma unroll
            for (int it = 0; it < 8; ++it) {
                const int c = it * 8 + gg;               // coalesced across gg
                float4 e = e4[c];
                float4 a = air[c]; ir  += e.x*a.x + e.y*a.y + e.z*a.z + e.w*a.w;
                float4 z = aiz[c]; iz  += e.x*z.x + e.y*z.y + e.z*z.z + e.w*z.w;
                float4 n = ain[c]; in_ += e.x*n.x + e.y*n.y + e.z*n.z + e.w*n.w;
            }
            float hr = 0.f, hz = 0.f, hn = 0.f;
            const float4* uhr = (const float4*)(w_hh + (size_t)gj * HDIM);
            const float4* uhz = (const float4*)(w_hh + (size_t)(gj + HDIM) * HDIM);
            const float4* uhn = (const float4*)(w_hh + (size_t)(gj + 2 * HDIM) * HDIM);
            const float*  hb  = s_hn + gb * 516;
            #pragma unroll 4
            for (int it = 0; it < 16; ++it) {
                const int c = it * 8 + gg;               // coalesced + LDS conflict-free
                float4 h = *(const float4*)&hb[c * 4];
                float4 a = uhr[c]; hr += h.x*a.x + h.y*a.y + h.z*a.z + h.w*a.w;
                float4 z = uhz[c]; hz += h.x*z.x + h.y*z.y + h.z*z.z + h.w*z.w;
                float4 n = uhn[c]; hn += h.x*n.x + h.y*n.y + h.z*n.z + h.w*n.w;
            }
            #pragma unroll
            for (int off = 1; off < 8; off <<= 1) {
                ir  += __shfl_xor_sync(~0u, ir,  off);
                iz  += __shfl_xor_sync(~0u, iz,  off);
                in_ += __shfl_xor_sync(~0u, in_, off);
                hr  += __shfl_xor_sync(~0u, hr,  off);
                hz  += __shfl_xor_sync(~0u, hz,  off);
                hn  += __shfl_xor_sync(~0u, hn,  off);
            }
            if (gg == 0) {
                const float hold = hb[gj];
                float hv;
                if (tok == PAD_ID || tok == EOS_ID) {
                    hv = hold;
                } else {
                    const float rg = 1.f / (1.f + expf(-(ir + b_ih[gj]            + hr + b_hh[gj])));
                    const float zg = 1.f / (1.f + expf(-(iz + b_ih[gj + HDIM]     + hz + b_hh[gj + HDIM])));
                    const float ng = tanhf(in_ + b_ih[gj + 2 * HDIM] + rg * (hn + b_hh[gj + 2 * HDIM]));
                    hv = (1.f - zg) * ng + zg * hold;
                }
                g_h[nxt][gb * HDIM + gj] = hv;
            }
        } else if (wp >= 8 && step > 0) {
            // Phase C for step-1 (off the critical path)
            const int b = wp - 8;
            float* o = out + ((size_t)(step - 1) * BATCH + b) * VOCAB + base;
            if (s_done[b]) {
                for (int r = lane; r < nrows; r += 32)
                    o[r] = (base + r == PAD_ID) ? 1.f : 0.f;
            } else {
                const float S = s_S[b];
                for (int r = lane; r < nrows; r += 32)
                    o[r] = __fdividef(__expf(s_log[r][b]), S);
            }
        }

        // ===== bar1: h ready =================================================
        __syncthreads();
        if (tid == 0) {
            red_release(&g_c1[0]);
            if (cta == 0) {
                while (ld_acquire(&g_c1[0]) < bt) {}
                st_release(&g_f1[0], bt);
            } else {
                while (ld_acquire(&g_f1[0]) < bt) {}
            }
        }
        __syncthreads();

        // ===== Stage h(nxt) into smem ========================================
        stage_h(g_h[nxt], s_h03, s_h47, s_hn, tid);
        __syncthreads();

        // ===== Phase B1: logits, 8 rows x 8 batches per warp (warps 0-13) ===
        if (wp < 14) {
            const int rb = min(wp * 8, nrows - 8);
            const float* wr = w_out + (size_t)(base + rb) * HDIM;
            ull v[32];
            #pragma unroll
            for (int i = 0; i < 32; i++) v[i] = 0ull;
            #pragma unroll 2
            for (int k = 0; k < 16; k++) {
                const int d = k * 32 + lane;
                const ulonglong2 hA = *(const ulonglong2*)&s_h03[d];
                const ulonglong2 hB = *(const ulonglong2*)&s_h47[d];
                #pragma unroll
                for (int r = 0; r < 8; r++) {
                    const ull wb = bcast2(wr[(size_t)r * HDIM + d]);
                    v[r*4+0] = fma2(wb, hA.x, v[r*4+0]);
                    v[r*4+1] = fma2(wb, hA.y, v[r*4+1]);
                    v[r*4+2] = fma2(wb, hB.x, v[r*4+2]);
                    v[r*4+3] = fma2(wb, hB.y, v[r*4+3]);
                }
            }
            #pragma unroll
            for (int i = 0; i < 16; i++) {
                ull g = (lane & 16) ? v[i] : v[i + 16];
                ull kp = (lane & 16) ? v[i + 16] : v[i];
                v[i] = add2(kp, __shfl_xor_sync(~0u, g, 16));
            }
            #pragma unroll
            for (int i = 0; i < 8; i++) {
                ull g = (lane & 8) ? v[i] : v[i + 8];
                ull kp = (lane & 8) ? v[i + 8] : v[i];
                v[i] = add2(kp, __shfl_xor_sync(~0u, g, 8));
            }
            #pragma unroll
            for (int i = 0; i < 4; i++) {
                ull g = (lane & 4) ? v[i] : v[i + 4];
                ull kp = (lane & 4) ? v[i + 4] : v[i];
                v[i] = add2(kp, __shfl_xor_sync(~0u, g, 4));
            }
            #pragma unroll
            for (int i = 0; i < 2; i++) {
                ull g = (lane & 2) ? v[i] : v[i + 2];
                ull kp = (lane & 2) ? v[i + 2] : v[i];
                v[i] = add2(kp, __shfl_xor_sync(~0u, g, 2));
            }
            {
                ull g = (lane & 1) ? v[0] : v[1];
                ull kp = (lane & 1) ? v[1] : v[0];
                v[0] = add2(kp, __shfl_xor_sync(~0u, g, 1));
            }
            const int r   = (lane >> 2) & 7;
            const int p   = lane & 3;
            const int row = rb + r;
            const float bo = b_out[base + row];
            const float2 lv = *(float2*)&v[0];
            s_log[row][2 * p]     = lv.x + bo;
            s_log[row][2 * p + 1] = lv.y + bo;
        }
        __syncthreads();

        // ===== per-CTA partial: sumexp + argmax (warps 0-7) ==================
        if (wp < BATCH) {
            const int b = wp;
            float m = -INFINITY, s = 0.f; int mi = 0x7fffffff;
            for (int r = lane; r < nrows; r += 32) {
                const float vv = s_log[r][b];
                s += __expf(vv);
                if (vv > m) { m = vv; mi = base + r; }
            }
            #pragma unroll
            for (int off = 16; off; off >>= 1) {
                const float om = __shfl_xor_sync(~0u, m, off);
                const int   oi = __shfl_xor_sync(~0u, mi, off);
                s += __shfl_xor_sync(~0u, s, off);
                if (om > m || (om == m && oi < mi)) { m = om; mi = oi; }
            }
            if (lane == 0) g_part[cta][b] = make_float4(m, s, __int_as_float(mi), 0.f);
        }

        // ===== bar2 + centralized global reduce in CTA 0 =====================
        __syncthreads();
        if (cta == 0) {
            if (tid == 0) {
                red_release(&g_c2[0]);
                while (ld_acquire(&g_c2[0]) < bt) {}
            }
            __syncthreads();          // whole CTA0 waits for counter-full
            if (wp < BATCH) {         // deterministic reduce over 148 partials
                const int b = wp;
                float m = -INFINITY, S = 0.f; int mi = 0x7fffffff;
                for (int c = lane; c < NCTA; c += 32) {
                    const float4 pr = __ldcg(&g_part[c][b]);
                    S += pr.y;
                    const int oi = __float_as_int(pr.z);
                    if (pr.x > m || (pr.x == m && oi < mi)) { m = pr.x; mi = oi; }
                }
                #pragma unroll
                for (int off = 16; off; off >>= 1) {
                    const float om = __shfl_xor_sync(~0u, m, off);
                    const int   oi = __shfl_xor_sync(~0u, mi, off);
                    S += __shfl_xor_sync(~0u, S, off);
                    if (om > m || (om == m && oi < mi)) { m = om; mi = oi; }
                }
                if (lane == 0) g_res[b] = make_uint2((unsigned)mi, __float_as_uint(S));
            }
            __syncthreads();
            if (tid == 0) st_release(&g_f2[0], bt);
        } else {
            if (tid == 0) { red_release(&g_c2[0]); while (ld_acquire(&g_f2[0]) < bt) {} }
            __syncthreads();
        }

        // ===== consume result: token/done/S ==================================
        if (tid < BATCH) {
            unsigned rx, ry;
            asm volatile("ld.global.cg.v2.u32 {%0,%1}, [%2];"
                         : "=r"(rx), "=r"(ry) : "l"(&g_res[tid]));
            const int old = s_tok[tid];
            const int d = (old == PAD_ID) | (old == EOS_ID);
            s_done[tid] = d;
            s_S[tid]    = __uint_as_float(ry);
            s_tok[tid]  = d ? PAD_ID : (int)rx;
        }
        __syncthreads();
    }

    // ===== Final Phase C: write last step's probabilities ====================
    {
        const int b  = tid >> 6;
        const int r0 = tid & 63;
        float* o = out + ((size_t)(lenseq - 1) * BATCH + b) * VOCAB + base;
        if (s_done[b]) {
            for (int r = r0; r < nrows; r += 64)
                o[r] = (base + r == PAD_ID) ? 1.f : 0.f;
        } else {
            const float S = s_S[b];
            for (int r = r0; r < nrows; r += 64)
                o[r] = __fdividef(__expf(s_log[r][b]), S);
        }
    }
}

extern "C" void kernel_launch(void* const* d_in, const int* in_sizes, int n_in,
                              void* d_out, int out_size) {
    const float* hidden    = (const float*)d_in[0];
    const float* embedding = (const float*)d_in[1];
    const float* w_ih      = (const float*)d_in[2];
    const float* w_hh      = (const float*)d_in[3];
    const float* b_ih      = (const float*)d_in[4];
    const float* b_hh      = (const float*)d_in[5];
    const float* w_out     = (const float*)d_in[6];
    const float* b_out     = (const float*)d_in[7];
    float* out = (float*)d_out;
    (void)in_sizes; (void)n_in;

    const int lenseq = out_size / (BATCH * VOCAB);
    if (lenseq <= 0) return;

    decoder_init<<<16, 256>>>(hidden);
    decoder_main<<<NCTA, TPB>>>(embedding, w_ih, w_hh, b_ih, b_hh,
                                w_out, b_out, out, lenseq);
}

// round 14
// speedup vs baseline: 1.8955x; 1.1655x over previous
#include <cuda_runtime.h>
#include <math.h>

// Greedy-collapsed beam search, persistent-grid decoder.
// Round-14: software pipeline across barriers — gh (=w_hh·h, token-independent)
// computed during the bar2 wait; GRU weights staged to smem once (101KB dynamic
// smem, 1 CTA/SM); barrier agents on idle warps; CTA0 reduce on warps 8-15.

#define NCTA  148
#define TPB   512
#define VOCAB 16000
#define EDIM  256
#define HDIM  512
#define BATCH 8
#define PAD_ID 0
#define SOS_ID 1
#define EOS_ID 2

typedef unsigned long long ull;

__device__ float    g_h[2][BATCH * HDIM];
__device__ float4   g_part[NCTA][BATCH];          // x=max, y=sumexp, z=argmax bits
__device__ __align__(128) unsigned g_c1[32];
__device__ __align__(128) unsigned g_f1[32];
__device__ __align__(128) unsigned g_c2[32];
__device__ __align__(128) unsigned g_f2[32];
__device__ __align__(128) uint2    g_res[BATCH];  // x=argmax token, y=S bits

// dynamic smem layout (float offsets)
#define SMF_H03   0                         // float4[512]  (2048 f)
#define SMF_H47   2048                      // float4[512]
#define SMF_HN    4096                      // 8*516
#define SMF_LOG   8224                      // 112*9
#define SMF_WIH   9232                      // 7 warps * 3 gates * 256
#define SMF_WHH   14608                     // 7 warps * 3 gates * 512
#define SMF_TOTAL 25360
#define SMEM_BYTES (SMF_TOTAL * 4)          // 101440

__global__ void decoder_init(const float* __restrict__ hidden) {
    int t = blockIdx.x * blockDim.x + threadIdx.x;
    if (t < BATCH * HDIM) g_h[0][t] = hidden[t];
    if (t == 0) { g_c1[0] = 0; g_f1[0] = 0; g_c2[0] = 0; g_f2[0] = 0; }
}

__device__ __forceinline__ ull fma2(ull a, ull b, ull c) {
    ull d; asm("fma.rn.f32x2 %0, %1, %2, %3;" : "=l"(d) : "l"(a), "l"(b), "l"(c)); return d;
}
__device__ __forceinline__ ull add2(ull a, ull b) {
    ull d; asm("add.rn.f32x2 %0, %1, %2;" : "=l"(d) : "l"(a), "l"(b)); return d;
}
__device__ __forceinline__ ull bcast2(float x) {
    ull d; asm("mov.b64 %0, {%1, %1};" : "=l"(d) : "r"(__float_as_uint(x))); return d;
}
__device__ __forceinline__ void red_release(unsigned* p) {
    asm volatile("red.release.gpu.global.add.u32 [%0], %1;" :: "l"(p), "r"(1u) : "memory");
}
__device__ __forceinline__ unsigned ld_acquire(unsigned* p) {
    unsigned v; asm volatile("ld.global.acquire.gpu.b32 %0, [%1];" : "=r"(v) : "l"(p) : "memory"); return v;
}
__device__ __forceinline__ void st_release(unsigned* p, unsigned v) {
    asm volatile("st.global.release.gpu.b32 [%0], %1;" :: "l"(p), "r"(v) : "memory");
}

// thread-per-dim transpose staging (TPB == HDIM), conflict-free
__device__ __forceinline__ void stage_h(const float* src, float* smf, int tid) {
    float v[BATCH];
    #pragma unroll
    for (int b = 0; b < BATCH; b++) v[b] = __ldcg(src + b * HDIM + tid);
    ((float4*)(smf + SMF_H03))[tid] = make_float4(v[0], v[1], v[2], v[3]);
    ((float4*)(smf + SMF_H47))[tid] = make_float4(v[4], v[5], v[6], v[7]);
    #pragma unroll
    for (int b = 0; b < BATCH; b++) smf[SMF_HN + b * 516 + tid] = v[b];
}

// gh = w_hh . h  partial sums (per lane, pre-reduce) — token-independent
__device__ __forceinline__ void gru_gh(const float* smf, int wp, int gb, int gg,
                                       float& hrp, float& hzp, float& hnp) {
    const float* hb = smf + SMF_HN + gb * 516;
    const float* wh = smf + SMF_WHH + wp * 1536;
    float r = 0.f, z = 0.f, n = 0.f;
    #pragma unroll 4
    for (int it = 0; it < 16; ++it) {
        const int c = it * 8 + gg;
        float4 h  = *(const float4*)(hb + c * 4);
        float4 ar = *(const float4*)(wh + c * 4);
        float4 az = *(const float4*)(wh + 512 + c * 4);
        float4 an = *(const float4*)(wh + 1024 + c * 4);
        r += h.x*ar.x + h.y*ar.y + h.z*ar.z + h.w*ar.w;
        z += h.x*az.x + h.y*az.y + h.z*az.z + h.w*az.w;
        n += h.x*an.x + h.y*an.y + h.z*an.z + h.w*an.w;
    }
    hrp = r; hzp = z; hnp = n;
}

__global__ void __launch_bounds__(TPB, 1) decoder_main(
    const float* __restrict__ embedding,
    const float* __restrict__ w_ih,
    const float* __restrict__ w_hh,
    const float* __restrict__ b_ih,
    const float* __restrict__ b_hh,
    const float* __restrict__ w_out,
    const float* __restrict__ b_out,
    float* __restrict__ out,
    int lenseq)
{
    extern __shared__ float smf[];
    __shared__ float s_S[BATCH];
    __shared__ int   s_tok[BATCH], s_done[BATCH];

    const int tid  = threadIdx.x;
    const int wp   = tid >> 5;
    const int lane = tid & 31;
    const int cta  = blockIdx.x;
    const int base  = cta * 108 + (cta < 16 ? cta : 16);
    const int nrows = 108 + (cta < 16 ? 1 : 0);

    // GRU tasks: one (j, batch-half) per warp, warps 0-6
    const int  task   = wp * NCTA + cta;
    const bool gru_on = (wp < 7) && (task < 2 * HDIM);
    const int  gj     = task >> 1;
    const int  gb     = (task & 1) * 4 + (lane >> 3);
    const int  gg     = lane & 7;

    // stage GRU weight slices into smem (once) + cache biases in regs
    float bi_r = 0.f, bi_z = 0.f, bi_n = 0.f, bh_r = 0.f, bh_z = 0.f, bh_n = 0.f;
    if (gru_on) {
        float* wi = smf + SMF_WIH + wp * 768;
        float* wh = smf + SMF_WHH + wp * 1536;
        #pragma unroll
        for (int g = 0; g < 3; ++g) {
            const float4* si = (const float4*)(w_ih + (size_t)(gj + g * HDIM) * EDIM);
            float4* di = (float4*)(wi + g * 256);
            for (int i = lane; i < 64; i += 32) di[i] = si[i];
            const float4* sh = (const float4*)(w_hh + (size_t)(gj + g * HDIM) * HDIM);
            float4* dh = (float4*)(wh + g * 512);
            for (int i = lane; i < 128; i += 32) dh[i] = sh[i];
        }
        bi_r = b_ih[gj]; bi_z = b_ih[gj + HDIM]; bi_n = b_ih[gj + 2 * HDIM];
        bh_r = b_hh[gj]; bh_z = b_hh[gj + HDIM]; bh_n = b_hh[gj + 2 * HDIM];
    }
    if (tid < BATCH) s_tok[tid] = SOS_ID;
    stage_h(g_h[0], smf, tid);
    __syncthreads();

    // prologue: gh for step 0
    float hrp = 0.f, hzp = 0.f, hnp = 0.f;
    if (gru_on) gru_gh(smf, wp, gb, gg, hrp, hzp, hnp);

    unsigned bt = 0;

    for (int step = 0; step < lenseq; ++step) {
        const int nxt = (step & 1) ^ 1;
        bt += NCTA;

        // ===== Phase 1: gi + gates (warps 0-6)  ||  C(step-1) (warps 8-15) ==
        if (gru_on) {
            const int tok = s_tok[gb];
            const float* wi = smf + SMF_WIH + wp * 768;
            const float4* e4 = (const float4*)(embedding + (size_t)tok * EDIM);
            float ir = 0.f, iz = 0.f, in_ = 0.f;
            #pragma unroll
            for (int it = 0; it < 8; ++it) {
                const int c = it * 8 + gg;
                float4 e  = e4[c];
                float4 ar = *(const float4*)(wi + c * 4);
                float4 az = *(const float4*)(wi + 256 + c * 4);
                float4 an = *(const float4*)(wi + 512 + c * 4);
                ir  += e.x*ar.x + e.y*ar.y + e.z*ar.z + e.w*ar.w;
                iz  += e.x*az.x + e.y*az.y + e.z*az.z + e.w*az.w;
                in_ += e.x*an.x + e.y*an.y + e.z*an.z + e.w*an.w;
            }
            float hr = hrp, hz = hzp, hn = hnp;
            #pragma unroll
            for (int off = 1; off < 8; off <<= 1) {
                ir  += __shfl_xor_sync(~0u, ir,  off);
                iz  += __shfl_xor_sync(~0u, iz,  off);
                in_ += __shfl_xor_sync(~0u, in_, off);
                hr  += __shfl_xor_sync(~0u, hr,  off);
                hz  += __shfl_xor_sync(~0u, hz,  off);
                hn  += __shfl_xor_sync(~0u, hn,  off);
            }
            if (gg == 0) {
                const float hold = smf[SMF_HN + gb * 516 + gj];
                float hv;
                if (tok == PAD_ID || tok == EOS_ID) {
                    hv = hold;
                } else {
                    const float rg = 1.f / (1.f + expf(-(ir + bi_r + hr + bh_r)));
                    const float zg = 1.f / (1.f + expf(-(iz + bi_z + hz + bh_z)));
                    const float ng = tanhf(in_ + bi_n + rg * (hn + bh_n));
                    hv = (1.f - zg) * ng + zg * hold;
                }
                g_h[nxt][gb * HDIM + gj] = hv;
            }
        } else if (wp >= 8 && step > 0) {
            const int b = wp - 8;
            float* o = out + ((size_t)(step - 1) * BATCH + b) * VOCAB + base;
            if (s_done[b]) {
                for (int r = lane; r < nrows; r += 32)
                    o[r] = (base + r == PAD_ID) ? 1.f : 0.f;
            } else {
                const float S = s_S[b];
                for (int r = lane; r < nrows; r += 32)
                    o[r] = __fdividef(__expf(smf[SMF_LOG + r * 9 + b]), S);
            }
        }

        // ===== bar1: h ready (agent = warp 7 lane 0) =========================
        __syncthreads();
        if (tid == 224) {
            red_release(&g_c1[0]);
            if (cta == 0) { while (ld_acquire(&g_c1[0]) < bt) {} st_release(&g_f1[0], bt); }
            else          { while (ld_acquire(&g_f1[0]) < bt) {} }
        }
        __syncthreads();

        stage_h(g_h[nxt], smf, tid);
        __syncthreads();

        // ===== B1: logits, 8 rows x 8 batches per warp (warps 0-13) =========
        if (wp < 14) {
            const int rb = min(wp * 8, nrows - 8);
            const float* wr = w_out + (size_t)(base + rb) * HDIM;
            ull v[32];
            #pragma unroll
            for (int i = 0; i < 32; i++) v[i] = 0ull;
            #pragma unroll 2
            for (int k = 0; k < 16; k++) {
                const int d = k * 32 + lane;
                const ulonglong2 hA = *(const ulonglong2*)(smf + SMF_H03 + d * 4);
                const ulonglong2 hB = *(const ulonglong2*)(smf + SMF_H47 + d * 4);
                #pragma unroll
                for (int r = 0; r < 8; r++) {
                    const ull wb = bcast2(wr[(size_t)r * HDIM + d]);
                    v[r*4+0] = fma2(wb, hA.x, v[r*4+0]);
                    v[r*4+1] = fma2(wb, hA.y, v[r*4+1]);
                    v[r*4+2] = fma2(wb, hB.x, v[r*4+2]);
                    v[r*4+3] = fma2(wb, hB.y, v[r*4+3]);
                }
            }
            #pragma unroll
            for (int i = 0; i < 16; i++) {
                ull g = (lane & 16) ? v[i] : v[i + 16];
                ull kp = (lane & 16) ? v[i + 16] : v[i];
                v[i] = add2(kp, __shfl_xor_sync(~0u, g, 16));
            }
            #pragma unroll
            for (int i = 0; i < 8; i++) {
                ull g = (lane & 8) ? v[i] : v[i + 8];
                ull kp = (lane & 8) ? v[i + 8] : v[i];
                v[i] = add2(kp, __shfl_xor_sync(~0u, g, 8));
            }
            #pragma unroll
            for (int i = 0; i < 4; i++) {
                ull g = (lane & 4) ? v[i] : v[i + 4];
                ull kp = (lane & 4) ? v[i + 4] : v[i];
                v[i] = add2(kp, __shfl_xor_sync(~0u, g, 4));
            }
            #pragma unroll
            for (int i = 0; i < 2; i++) {
                ull g = (lane & 2) ? v[i] : v[i + 2];
                ull kp = (lane & 2) ? v[i + 2] : v[i];
                v[i] = add2(kp, __shfl_xor_sync(~0u, g, 2));
            }
            {
                ull g = (lane & 1) ? v[0] : v[1];
                ull kp = (lane & 1) ? v[1] : v[0];
                v[0] = add2(kp, __shfl_xor_sync(~0u, g, 1));
            }
            const int r   = (lane >> 2) & 7;
            const int p   = lane & 3;
            const int row = rb + r;
            const float bo = b_out[base + row];
            const float2 lv = *(float2*)&v[0];
            smf[SMF_LOG + row * 9 + 2 * p]     = lv.x + bo;
            smf[SMF_LOG + row * 9 + 2 * p + 1] = lv.y + bo;
        }
        __syncthreads();

        // ===== per-CTA partial (warps 0-7) ===================================
        if (wp < BATCH) {
            const int b = wp;
            float m = -INFINITY, s = 0.f; int mi = 0x7fffffff;
            for (int r = lane; r < nrows; r += 32) {
                const float vv = smf[SMF_LOG + r * 9 + b];
                s += __expf(vv);
                if (vv > m) { m = vv; mi = base + r; }
            }
            #pragma unroll
            for (int off = 16; off; off >>= 1) {
                const float om = __shfl_xor_sync(~0u, m, off);
                const int   oi = __shfl_xor_sync(~0u, mi, off);
                s += __shfl_xor_sync(~0u, s, off);
                if (om > m || (om == m && oi < mi)) { m = om; mi = oi; }
            }
            if (lane == 0) g_part[cta][b] = make_float4(m, s, __int_as_float(mi), 0.f);
        }
        __syncthreads();

        // ===== bar2 + centralized reduce, gh(next) overlapped ================
        if (cta == 0) {
            if (tid == 256) {
                red_release(&g_c2[0]);
                while (ld_acquire(&g_c2[0]) < bt) {}
            }
            if (wp >= 8) {
                asm volatile("bar.sync 1, 256;" ::: "memory");
                const int b = wp - 8;
                float m = -INFINITY, S = 0.f; int mi = 0x7fffffff;
                for (int c = lane; c < NCTA; c += 32) {
                    const float4 pr = __ldcg(&g_part[c][b]);
                    S += pr.y;
                    const int oi = __float_as_int(pr.z);
                    if (pr.x > m || (pr.x == m && oi < mi)) { m = pr.x; mi = oi; }
                }
                #pragma unroll
                for (int off = 16; off; off >>= 1) {
                    const float om = __shfl_xor_sync(~0u, m, off);
                    const int   oi = __shfl_xor_sync(~0u, mi, off);
                    S += __shfl_xor_sync(~0u, S, off);
                    if (om > m || (om == m && oi < mi)) { m = om; mi = oi; }
                }
                if (lane == 0) g_res[b] = make_uint2((unsigned)mi, __float_as_uint(S));
                asm volatile("bar.sync 1, 256;" ::: "memory");
                if (tid == 256) st_release(&g_f2[0], bt);
            }
            if (gru_on) gru_gh(smf, wp, gb, gg, hrp, hzp, hnp);
        } else {
            if (tid == 224) {
                red_release(&g_c2[0]);
                while (ld_acquire(&g_f2[0]) < bt) {}
            }
            if (gru_on) gru_gh(smf, wp, gb, gg, hrp, hzp, hnp);
        }
        __syncthreads();

        // ===== consume: token / done / S =====================================
        if (tid < BATCH) {
            unsigned rx, ry;
            asm volatile("ld.global.cg.v2.u32 {%0,%1}, [%2];"
                         : "=r"(rx), "=r"(ry) : "l"(&g_res[tid]));
            const int old = s_tok[tid];
            const int d = (old == PAD_ID) | (old == EOS_ID);
            s_done[tid] = d;
            s_S[tid]    = __uint_as_float(ry);
            s_tok[tid]  = d ? PAD_ID : (int)rx;
        }
        __syncthreads();
    }

    // ===== final C: write last step's probabilities ==========================
    {
        const int b  = tid >> 6;
        const int r0 = tid & 63;
        float* o = out + ((size_t)(lenseq - 1) * BATCH + b) * VOCAB + base;
        if (s_done[b]) {
            for (int r = r0; r < nrows; r += 64)
                o[r] = (base + r == PAD_ID) ? 1.f : 0.f;
        } else {
            const float S = s_S[b];
            for (int r = r0; r < nrows; r += 64)
                o[r] = __fdividef(__expf(smf[SMF_LOG + r * 9 + b]), S);
        }
    }
}

extern "C" void kernel_launch(void* const* d_in, const int* in_sizes, int n_in,
                              void* d_out, int out_size) {
    const float* hidden    = (const float*)d_in[0];
    const float* embedding = (const float*)d_in[1];
    const float* w_ih      = (const float*)d_in[2];
    const float* w_hh      = (const float*)d_in[3];
    const float* b_ih      = (const float*)d_in[4];
    const float* b_hh      = (const float*)d_in[5];
    const float* w_out     = (const float*)d_in[6];
    const float* b_out     = (const float*)d_in[7];
    float* out = (float*)d_out;
    (void)in_sizes; (void)n_in;

    const int lenseq = out_size / (BATCH * VOCAB);
    if (lenseq <= 0) return;

    cudaFuncSetAttribute(decoder_main, cudaFuncAttributeMaxDynamicSharedMemorySize, SMEM_BYTES);
    decoder_init<<<16, 256>>>(hidden);
    decoder_main<<<NCTA, TPB, SMEM_BYTES>>>(embedding, w_ih, w_hh, b_ih, b_hh,
                                            w_out, b_out, out, lenseq);
}